// round 3
// baseline (speedup 1.0000x reference)
#include <cuda_runtime.h>
#include <cuda_bf16.h>
#include <cstdint>

#define B_      32
#define M_      512
#define S_      10
#define V_      32000
#define D_      128
#define HOPS_   3
#define NSPL    32                 // m-splits per batch
#define MB      16                 // m rows per block
#define NBLK    (B_ * NSPL)        // 1024 blocks, single wave (8/SM * 148 = 1184)
#define THREADS 128

// Global scratch (small): per-block partials + running query + barrier ticket
__device__ __align__(16) float g_part[NBLK * D_];
__device__ float g_den[NBLK];
__device__ __align__(16) float g_u[B_ * D_];
__device__ unsigned int g_tick;    // monotonic across barriers AND graph replays

__device__ __forceinline__ float warpSum(float v) {
    #pragma unroll
    for (int o = 16; o > 0; o >>= 1) v += __shfl_xor_sync(0xffffffffu, v, o);
    return v;
}

// Ticket grid barrier: monotonic counter, no reset, replay-safe.
// Valid because all NBLK blocks are co-resident (one wave) and barriers are
// globally ordered, so round-k arrivals form a contiguous NBLK-sized range.
__device__ __forceinline__ void gridbar()
{
    __threadfence();               // release this thread's global writes
    __syncthreads();
    if (threadIdx.x == 0) {
        const unsigned arrive = atomicAdd(&g_tick, 1u) + 1u;
        const unsigned target = ((arrive + NBLK - 1u) / NBLK) * NBLK;
        while (*((volatile unsigned*)&g_tick) < target) __nanosleep(32);
    }
    __syncthreads();
    __threadfence();               // acquire before reading peers' writes
}

__global__ void __launch_bounds__(THREADS, 8)
k_fused(const int* __restrict__ story, const float* __restrict__ hidden,
        const float* __restrict__ C, float* __restrict__ out)
{
    __shared__ __align__(16) float s_bag[HOPS_][MB][D_];   // 24 KB: tables C[1..3]
    __shared__ __align__(16) float s_tmp[4][D_];
    __shared__ float s_logit[MB];
    __shared__ float s_denw[4];

    const int blk  = blockIdx.x;
    const int b    = blk >> 5;          // / NSPL
    const int sp   = blk & (NSPL - 1);
    const int tid  = threadIdx.x;
    const int lane = tid & 31;
    const int wid  = tid >> 5;          // 0..3

    const float4  u0 = reinterpret_cast<const float4*>(hidden + (size_t)b * D_)[lane];
    const float4* C4 = reinterpret_cast<const float4*>(C);
    const size_t  tabstr = (size_t)V_ * (D_ / 4);

    // ---------------- gather: 4 m per warp, all 4 tables, bags stay in SMEM --
    #pragma unroll
    for (int i = 0; i < 4; i++) {
        const int ml = wid * 4 + i;
        const int m  = sp * MB + ml;
        int tok = 0;
        if (lane < S_) tok = story[((size_t)b * M_ + m) * S_ + lane];

        float4 a0 = make_float4(0.f, 0.f, 0.f, 0.f);
        float4 a1 = a0, a2 = a0, a3 = a0;
        #pragma unroll
        for (int s = 0; s < S_; s++) {
            const int t = __shfl_sync(0xffffffffu, tok, s);
            const size_t base = (size_t)t * (D_ / 4) + lane;
            const float4 r0 = C4[base];
            const float4 r1 = C4[base + tabstr];
            const float4 r2 = C4[base + 2 * tabstr];
            const float4 r3 = C4[base + 3 * tabstr];
            a0.x += r0.x; a0.y += r0.y; a0.z += r0.z; a0.w += r0.w;
            a1.x += r1.x; a1.y += r1.y; a1.z += r1.z; a1.w += r1.w;
            a2.x += r2.x; a2.y += r2.y; a2.z += r2.z; a2.w += r2.w;
            a3.x += r3.x; a3.y += r3.y; a3.z += r3.z; a3.w += r3.w;
        }

        // hop-0 logit: dot(table0 bag, u0)
        float d = a0.x * u0.x + a0.y * u0.y + a0.z * u0.z + a0.w * u0.w;
        d = warpSum(d);
        if (lane == 0) s_logit[ml] = d;

        reinterpret_cast<float4*>(&s_bag[0][ml][0])[lane] = a1;
        reinterpret_cast<float4*>(&s_bag[1][ml][0])[lane] = a2;
        reinterpret_cast<float4*>(&s_bag[2][ml][0])[lane] = a3;
    }
    __syncthreads();

    // ---------------- 3 hops, bags read from SMEM ---------------------------
    for (int h = 0; h < HOPS_; h++) {
        // unnormalized partial combine over this block's 16 m
        float4 acc = make_float4(0.f, 0.f, 0.f, 0.f);
        float  denp = 0.f;
        #pragma unroll
        for (int i = 0; i < 4; i++) {
            const int ml = wid * 4 + i;
            const float e = __expf(s_logit[ml]);
            const float4 v = reinterpret_cast<const float4*>(&s_bag[h][ml][0])[lane];
            acc.x += e * v.x; acc.y += e * v.y;
            acc.z += e * v.z; acc.w += e * v.w;
            denp += e;
        }
        reinterpret_cast<float4*>(&s_tmp[wid][0])[lane] = acc;
        if (lane == 0) s_denw[wid] = denp;
        __syncthreads();

        g_part[(size_t)blk * D_ + tid] =
            s_tmp[0][tid] + s_tmp[1][tid] + s_tmp[2][tid] + s_tmp[3][tid];
        if (tid == 0) g_den[blk] = s_denw[0] + s_denw[1] + s_denw[2] + s_denw[3];

        gridbar();

        // one reducer block per batch: u_{h+1} = u_h + (Σ e·bag)/(Σ e)
        if (sp == 0) {
            float den = 0.f, num = 0.f;
            #pragma unroll
            for (int s2 = 0; s2 < NSPL; s2++) den += g_den[b * NSPL + s2];
            #pragma unroll
            for (int s2 = 0; s2 < NSPL; s2++)
                num += g_part[((size_t)b * NSPL + s2) * D_ + tid];
            const float u = ((h == 0) ? hidden[(size_t)b * D_ + tid]
                                      : g_u[(size_t)b * D_ + tid]) + num / den;
            g_u[(size_t)b * D_ + tid] = u;
            if (h == HOPS_ - 1)
                out[(size_t)B_ * M_ + (size_t)b * D_ + tid] = u;   // final u
        }
        if (h == HOPS_ - 1) break;

        gridbar();

        // next logits: dot(bag_h[m], u_{h+1}) from SMEM-cached bags
        const float4 u4 = reinterpret_cast<const float4*>(g_u + (size_t)b * D_)[lane];
        #pragma unroll
        for (int i = 0; i < 4; i++) {
            const int ml = wid * 4 + i;
            const float4 v = reinterpret_cast<const float4*>(&s_bag[h][ml][0])[lane];
            float d = v.x * u4.x + v.y * u4.y + v.z * u4.z + v.w * u4.w;
            d = warpSum(d);
            if (lane == 0) {
                s_logit[ml] = d;
                if (h == 1)   // logits entering the final hop == output prob_logit
                    out[(size_t)b * M_ + sp * MB + ml] = d;
            }
        }
        __syncthreads();
    }
}

extern "C" void kernel_launch(void* const* d_in, const int* in_sizes, int n_in,
                              void* d_out, int out_size)
{
    const int*   story  = (const int*)  d_in[0];   // [B, M, S] int32
    const float* hidden = (const float*)d_in[1];   // [B, 1, D] f32
    const float* C      = (const float*)d_in[2];   // [4, V, D] f32
    float* out = (float*)d_out;                    // [B*M] logits ++ [B*D] u

    k_fused<<<NBLK, THREADS>>>(story, hidden, C, out);
}

// round 5
// speedup vs baseline: 1.1519x; 1.1519x over previous
#include <cuda_runtime.h>
#include <cuda_fp16.h>
#include <cstdint>

#define B_    32
#define M_    512
#define S_    10
#define V_    32000
#define D_    128
#define HOPS_ 3

#define GBLK  2048            // gather blocks (8 warps, 1 m per warp)
#define FSPL  16              // m-splits per batch in k_F -> 512 blocks, 32 m/block

// Bags for tables 1..3 in fp16, packed 4 dims per uint2 (32 uint2 per row).
__device__ __align__(16) uint2 g_bagh[3u * B_ * M_ * (D_ / 4)];   // 12.6 MB
// Hop-0 partials from gather (per gather block), hop-1/2 partials from k_F.
__device__ __align__(16) float g_part0[GBLK * D_];
__device__ float g_den0[GBLK];
__device__ __align__(16) float g_partF[B_ * FSPL * D_];
__device__ float g_denF[B_ * FSPL];
__device__ __align__(16) float g_u[B_ * D_];   // running query

__device__ __forceinline__ float warpSum(float v) {
    #pragma unroll
    for (int o = 16; o > 0; o >>= 1) v += __shfl_xor_sync(0xffffffffu, v, o);
    return v;
}
__device__ __forceinline__ uint2 pack4(float4 v) {
    __half2 lo = __floats2half2_rn(v.x, v.y);
    __half2 hi = __floats2half2_rn(v.z, v.w);
    uint2 r;
    r.x = *reinterpret_cast<unsigned*>(&lo);
    r.y = *reinterpret_cast<unsigned*>(&hi);
    return r;
}
__device__ __forceinline__ float4 unpack4(uint2 p) {
    __half2 lo = *reinterpret_cast<__half2*>(&p.x);
    __half2 hi = *reinterpret_cast<__half2*>(&p.y);
    float2 l = __half22float2(lo);
    float2 h = __half22float2(hi);
    return make_float4(l.x, l.y, h.x, h.y);
}

// ---------------------------------------------------------------------------
// Gather: one warp per (b,m) (R2 shape: max MLP). Sums rows of all 4 tables.
// Fuses the ENTIRE hop-0 body: logit0 = bag0·u0, e = exp(logit0),
// per-block partial num0 += e*bag1, den0 += e. Bags 1..3 stored as fp16.
// ---------------------------------------------------------------------------
__global__ void __launch_bounds__(256) k_gather(const int* __restrict__ story,
                                                const float* __restrict__ hidden,
                                                const float* __restrict__ C)
{
    __shared__ __align__(16) float s_pt[8][D_];
    __shared__ float s_den[8];

    const int warp = (blockIdx.x * blockDim.x + threadIdx.x) >> 5;
    const int lane = threadIdx.x & 31;
    const int wid  = threadIdx.x >> 5;
    const int b = warp / M_;
    const int m = warp % M_;

    int tok = 0;
    if (lane < S_) tok = story[((size_t)b * M_ + m) * S_ + lane];

    float4 a0 = make_float4(0.f, 0.f, 0.f, 0.f);
    float4 a1 = a0, a2 = a0, a3 = a0;

    const float4* C4 = reinterpret_cast<const float4*>(C);
    const size_t tabstr = (size_t)V_ * (D_ / 4);

    #pragma unroll
    for (int s = 0; s < S_; s++) {
        const int t = __shfl_sync(0xffffffffu, tok, s);
        const size_t base = (size_t)t * (D_ / 4) + lane;
        const float4 r0 = C4[base];
        const float4 r1 = C4[base + tabstr];
        const float4 r2 = C4[base + 2 * tabstr];
        const float4 r3 = C4[base + 3 * tabstr];
        a0.x += r0.x; a0.y += r0.y; a0.z += r0.z; a0.w += r0.w;
        a1.x += r1.x; a1.y += r1.y; a1.z += r1.z; a1.w += r1.w;
        a2.x += r2.x; a2.y += r2.y; a2.z += r2.z; a2.w += r2.w;
        a3.x += r3.x; a3.y += r3.y; a3.z += r3.z; a3.w += r3.w;
    }

    // hop-0: logit, exp, partial combine over bag1 (all in registers)
    const float4 u4 = reinterpret_cast<const float4*>(hidden + (size_t)b * D_)[lane];
    float d = a0.x * u4.x + a0.y * u4.y + a0.z * u4.z + a0.w * u4.w;
    d = warpSum(d);
    const float e = __expf(d);
    reinterpret_cast<float4*>(&s_pt[wid][0])[lane] =
        make_float4(e * a1.x, e * a1.y, e * a1.z, e * a1.w);
    if (lane == 0) s_den[wid] = e;

    // store fp16 bags
    const size_t row = ((size_t)b * M_ + m) * (D_ / 4) + lane;
    const size_t bstr = (size_t)B_ * M_ * (D_ / 4);
    g_bagh[row]            = pack4(a1);
    g_bagh[row + bstr]     = pack4(a2);
    g_bagh[row + 2 * bstr] = pack4(a3);

    __syncthreads();
    const int tid = threadIdx.x;
    if (tid < D_) {
        float v = 0.f;
        #pragma unroll
        for (int g = 0; g < 8; g++) v += s_pt[g][tid];
        g_part0[(size_t)blockIdx.x * D_ + tid] = v;
    }
    if (tid == 0) {
        float dn = 0.f;
        #pragma unroll
        for (int g = 0; g < 8; g++) dn += s_den[g];
        g_den0[blockIdx.x] = dn;
    }
}

// ---------------------------------------------------------------------------
// Reduce: u_{h+1} = base + (Σ num partials)/(Σ den partials). Fixed order,
// no atomics. npart==64 -> gather partials (64/batch), else k_F (16/batch).
// ---------------------------------------------------------------------------
__global__ void __launch_bounds__(128) k_red(const float* __restrict__ hidden,
                                             float* __restrict__ out,
                                             int npart, int use_hidden, int write_u)
{
    const int b   = blockIdx.x;
    const int tid = threadIdx.x;
    const float* part = (npart == 64) ? g_part0 : g_partF;
    const float* den  = (npart == 64) ? g_den0  : g_denF;

    float dn = 0.f;
    for (int k = 0; k < npart; k++) dn += den[b * npart + k];
    float num = 0.f;
    for (int k = 0; k < npart; k++) num += part[((size_t)b * npart + k) * D_ + tid];

    const float base = use_hidden ? hidden[(size_t)b * D_ + tid]
                                  : g_u[(size_t)b * D_ + tid];
    const float u = base + num / dn;
    g_u[(size_t)b * D_ + tid] = u;
    if (write_u) out[(size_t)B_ * M_ + (size_t)b * D_ + tid] = u;
}

// ---------------------------------------------------------------------------
// Full hop body in one pass: for each m, logit = bagA[m]·u, e = exp(logit),
// num += e*bagB[m], den += e. Optionally writes logits to output (final hop).
// grid = B*FSPL (512), 8 warps/block, 4 m per warp.
// ---------------------------------------------------------------------------
__global__ void __launch_bounds__(256) k_F(float* __restrict__ out,
                                           int tabA, int tabB, int wlog)
{
    __shared__ __align__(16) float s_pt[8][D_];
    __shared__ float s_den[8];

    const int blk  = blockIdx.x;
    const int b    = blk / FSPL;
    const int sp   = blk % FSPL;
    const int tid  = threadIdx.x;
    const int lane = tid & 31;
    const int wid  = tid >> 5;

    const float4 u4 = reinterpret_cast<const float4*>(g_u + (size_t)b * D_)[lane];
    const size_t bstr = (size_t)B_ * M_ * (D_ / 4);
    const size_t rbase = (size_t)(b * M_ + sp * 32) * (D_ / 4) + lane;

    float4 acc = make_float4(0.f, 0.f, 0.f, 0.f);
    float den = 0.f;
    #pragma unroll
    for (int i = 0; i < 4; i++) {
        const int ml = wid * 4 + i;                 // 0..31 within block
        const size_t row = rbase + (size_t)ml * (D_ / 4);
        const float4 va = unpack4(g_bagh[(size_t)tabA * bstr + row]);
        const float4 vb = unpack4(g_bagh[(size_t)tabB * bstr + row]);
        float d = va.x * u4.x + va.y * u4.y + va.z * u4.z + va.w * u4.w;
        d = warpSum(d);
        const float e = __expf(d);
        if (wlog && lane == 0) out[(size_t)b * M_ + sp * 32 + ml] = d;
        acc.x += e * vb.x; acc.y += e * vb.y;
        acc.z += e * vb.z; acc.w += e * vb.w;
        den += e;
    }
    reinterpret_cast<float4*>(&s_pt[wid][0])[lane] = acc;
    if (lane == 0) s_den[wid] = den;
    __syncthreads();

    if (tid < D_) {
        float v = 0.f;
        #pragma unroll
        for (int g = 0; g < 8; g++) v += s_pt[g][tid];
        g_partF[(size_t)blk * D_ + tid] = v;
    }
    if (tid == 0) {
        float dn = 0.f;
        #pragma unroll
        for (int g = 0; g < 8; g++) dn += s_den[g];
        g_denF[blk] = dn;
    }
}

extern "C" void kernel_launch(void* const* d_in, const int* in_sizes, int n_in,
                              void* d_out, int out_size)
{
    const int*   story  = (const int*)  d_in[0];   // [B, M, S] int32
    const float* hidden = (const float*)d_in[1];   // [B, 1, D] f32
    const float* C      = (const float*)d_in[2];   // [4, V, D] f32
    float* out = (float*)d_out;                    // [B*M] logits ++ [B*D] u

    k_gather<<<GBLK, 256>>>(story, hidden, C);         // hop-0 F fused in
    k_red   <<<B_, 128>>>(hidden, out, 64, 1, 0);      // u1
    k_F     <<<B_ * FSPL, 256>>>(out, 0, 1, 0);        // hop 1 (bags of C1, C2)
    k_red   <<<B_, 128>>>(hidden, out, FSPL, 0, 0);    // u2
    k_F     <<<B_ * FSPL, 256>>>(out, 1, 2, 1);        // hop 2, writes prob_logit
    k_red   <<<B_, 128>>>(hidden, out, FSPL, 0, 1);    // u3 -> output
}

// round 6
// speedup vs baseline: 1.2676x; 1.1004x over previous
#include <cuda_runtime.h>
#include <cuda_fp16.h>
#include <cstdint>

#define B_    32
#define M_    512
#define S_    10
#define V_    32000
#define D_    128

#define GBLK  2048            // gather blocks (8 warps, 1 m per warp)
#define GPB   64              // gather blocks per batch (partials per batch)
#define FSPL  16              // m-splits per batch in k_F -> 512 blocks, 32 m/block

// Bags for tables 1..3 in fp16, packed 4 dims per uint2.
__device__ __align__(16) uint2 g_bagh[3u * B_ * M_ * (D_ / 4)];   // 12.6 MB
__device__ __align__(16) float g_part0[GBLK * D_];    // hop-0 partials (gather)
__device__ float g_den0[GBLK];
__device__ __align__(16) float g_partF[B_ * FSPL * D_]; // hop partials (k_F)
__device__ float g_denF[B_ * FSPL];
__device__ __align__(16) float g_u[B_ * D_];          // u1 (published by k_F1)
__device__ unsigned int g_cnt[B_];                    // k_F2 arrival counters (self-reset)

__device__ __forceinline__ float warpSum(float v) {
    #pragma unroll
    for (int o = 16; o > 0; o >>= 1) v += __shfl_xor_sync(0xffffffffu, v, o);
    return v;
}
__device__ __forceinline__ uint2 pack4(float4 v) {
    __half2 lo = __floats2half2_rn(v.x, v.y);
    __half2 hi = __floats2half2_rn(v.z, v.w);
    uint2 r;
    r.x = *reinterpret_cast<unsigned*>(&lo);
    r.y = *reinterpret_cast<unsigned*>(&hi);
    return r;
}
__device__ __forceinline__ float4 unpack4(uint2 p) {
    __half2 lo = *reinterpret_cast<__half2*>(&p.x);
    __half2 hi = *reinterpret_cast<__half2*>(&p.y);
    float2 l = __half22float2(lo);
    float2 h = __half22float2(hi);
    return make_float4(l.x, l.y, h.x, h.y);
}

// ---------------------------------------------------------------------------
// Gather: one warp per (b,m). Sums rows of all 4 tables; fuses hop-0 body
// (logit0 = bag0·u0, e = exp, partial num/den). Bags 1..3 stored fp16.
// ---------------------------------------------------------------------------
__global__ void __launch_bounds__(256) k_gather(const int* __restrict__ story,
                                                const float* __restrict__ hidden,
                                                const float* __restrict__ C)
{
    __shared__ __align__(16) float s_pt[8][D_];
    __shared__ float s_den[8];

    const int warp = (blockIdx.x * blockDim.x + threadIdx.x) >> 5;
    const int lane = threadIdx.x & 31;
    const int wid  = threadIdx.x >> 5;
    const int b = warp / M_;
    const int m = warp % M_;

    int tok = 0;
    if (lane < S_) tok = story[((size_t)b * M_ + m) * S_ + lane];

    float4 a0 = make_float4(0.f, 0.f, 0.f, 0.f);
    float4 a1 = a0, a2 = a0, a3 = a0;

    const float4* C4 = reinterpret_cast<const float4*>(C);
    const size_t tabstr = (size_t)V_ * (D_ / 4);

    #pragma unroll
    for (int s = 0; s < S_; s++) {
        const int t = __shfl_sync(0xffffffffu, tok, s);
        const size_t base = (size_t)t * (D_ / 4) + lane;
        const float4 r0 = C4[base];
        const float4 r1 = C4[base + tabstr];
        const float4 r2 = C4[base + 2 * tabstr];
        const float4 r3 = C4[base + 3 * tabstr];
        a0.x += r0.x; a0.y += r0.y; a0.z += r0.z; a0.w += r0.w;
        a1.x += r1.x; a1.y += r1.y; a1.z += r1.z; a1.w += r1.w;
        a2.x += r2.x; a2.y += r2.y; a2.z += r2.z; a2.w += r2.w;
        a3.x += r3.x; a3.y += r3.y; a3.z += r3.z; a3.w += r3.w;
    }

    const float4 u4 = reinterpret_cast<const float4*>(hidden + (size_t)b * D_)[lane];
    float d = a0.x * u4.x + a0.y * u4.y + a0.z * u4.z + a0.w * u4.w;
    d = warpSum(d);
    const float e = __expf(d);
    reinterpret_cast<float4*>(&s_pt[wid][0])[lane] =
        make_float4(e * a1.x, e * a1.y, e * a1.z, e * a1.w);
    if (lane == 0) s_den[wid] = e;

    const size_t row = ((size_t)b * M_ + m) * (D_ / 4) + lane;
    const size_t bstr = (size_t)B_ * M_ * (D_ / 4);
    g_bagh[row]            = pack4(a1);
    g_bagh[row + bstr]     = pack4(a2);
    g_bagh[row + 2 * bstr] = pack4(a3);

    __syncthreads();
    const int tid = threadIdx.x;
    if (tid < D_) {
        float v = 0.f;
        #pragma unroll
        for (int g = 0; g < 8; g++) v += s_pt[g][tid];
        g_part0[(size_t)blockIdx.x * D_ + tid] = v;
    }
    if (tid == 0) {
        float dn = 0.f;
        #pragma unroll
        for (int g = 0; g < 8; g++) dn += s_den[g];
        g_den0[blockIdx.x] = dn;
    }
}

// ---------------------------------------------------------------------------
// k_F1: redundantly reduce gather partials -> u1 (SMEM); run hop-1 pass
// (logit = bag1·u1, e, num += e*bag2, den += e); write hop-1 partials.
// sp==0 block publishes u1 to g_u for k_F2.
// ---------------------------------------------------------------------------
__global__ void __launch_bounds__(256) k_F1(const float* __restrict__ hidden)
{
    __shared__ __align__(16) float s_u[D_];
    __shared__ __align__(16) float s_pt[8][D_];
    __shared__ float s_den[8];

    const int blk  = blockIdx.x;
    const int b    = blk / FSPL;
    const int sp   = blk % FSPL;
    const int tid  = threadIdx.x;
    const int lane = tid & 31;
    const int wid  = tid >> 5;

    // ---- u1 = hidden + (Σ num0)/(Σ den0), redundant per block ----
    if (tid < D_) {
        float dn = 0.f;
        #pragma unroll 8
        for (int k = 0; k < GPB; k++) dn += g_den0[b * GPB + k];
        float num = 0.f;
        #pragma unroll 8
        for (int k = 0; k < GPB; k++) num += g_part0[((size_t)b * GPB + k) * D_ + tid];
        s_u[tid] = hidden[(size_t)b * D_ + tid] + num / dn;
        if (sp == 0) g_u[(size_t)b * D_ + tid] = s_u[tid];
    }
    __syncthreads();

    // ---- hop-1 pass over this block's 32 m ----
    const float4 u4 = reinterpret_cast<const float4*>(s_u)[lane];
    const size_t bstr = (size_t)B_ * M_ * (D_ / 4);
    const size_t rbase = (size_t)(b * M_ + sp * 32) * (D_ / 4) + lane;

    float4 acc = make_float4(0.f, 0.f, 0.f, 0.f);
    float den = 0.f;
    #pragma unroll
    for (int i = 0; i < 4; i++) {
        const int ml = wid * 4 + i;
        const size_t row = rbase + (size_t)ml * (D_ / 4);
        const float4 va = unpack4(g_bagh[row]);               // table C1
        const float4 vb = unpack4(g_bagh[bstr + row]);        // table C2
        float d = va.x * u4.x + va.y * u4.y + va.z * u4.z + va.w * u4.w;
        d = warpSum(d);
        const float e = __expf(d);
        acc.x += e * vb.x; acc.y += e * vb.y;
        acc.z += e * vb.z; acc.w += e * vb.w;
        den += e;
    }
    reinterpret_cast<float4*>(&s_pt[wid][0])[lane] = acc;
    if (lane == 0) s_den[wid] = den;
    __syncthreads();

    if (tid < D_) {
        float v = 0.f;
        #pragma unroll
        for (int g = 0; g < 8; g++) v += s_pt[g][tid];
        g_partF[(size_t)blk * D_ + tid] = v;
    }
    if (tid == 0) {
        float dn = 0.f;
        #pragma unroll
        for (int g = 0; g < 8; g++) dn += s_den[g];
        g_denF[blk] = dn;
    }
}

// ---------------------------------------------------------------------------
// k_F2: redundantly reduce hop-1 partials -> u2 (SMEM); run hop-2 pass,
// writing logits (prob_logit output). Last-arriving block per batch reduces
// hop-2 partials and writes final u3 to out. Counter self-resets.
// ---------------------------------------------------------------------------
__global__ void __launch_bounds__(256) k_F2(float* __restrict__ out)
{
    __shared__ __align__(16) float s_u[D_];
    __shared__ __align__(16) float s_pt[8][D_];
    __shared__ float s_den[8];
    __shared__ int s_last;

    const int blk  = blockIdx.x;
    const int b    = blk / FSPL;
    const int sp   = blk % FSPL;
    const int tid  = threadIdx.x;
    const int lane = tid & 31;
    const int wid  = tid >> 5;

    // ---- u2 = u1 + (Σ numF)/(Σ denF), redundant per block ----
    if (tid < D_) {
        float dn = 0.f;
        #pragma unroll
        for (int k = 0; k < FSPL; k++) dn += g_denF[b * FSPL + k];
        float num = 0.f;
        #pragma unroll
        for (int k = 0; k < FSPL; k++) num += g_partF[((size_t)b * FSPL + k) * D_ + tid];
        s_u[tid] = g_u[(size_t)b * D_ + tid] + num / dn;
    }
    __syncthreads();

    // ---- hop-2 pass: logits -> OUTPUT; partials for u3 ----
    const float4 u4 = reinterpret_cast<const float4*>(s_u)[lane];
    const size_t bstr = (size_t)B_ * M_ * (D_ / 4);
    const size_t rbase = (size_t)(b * M_ + sp * 32) * (D_ / 4) + lane;

    float4 acc = make_float4(0.f, 0.f, 0.f, 0.f);
    float den = 0.f;
    #pragma unroll
    for (int i = 0; i < 4; i++) {
        const int ml = wid * 4 + i;
        const size_t row = rbase + (size_t)ml * (D_ / 4);
        const float4 va = unpack4(g_bagh[bstr + row]);        // table C2
        const float4 vb = unpack4(g_bagh[2 * bstr + row]);    // table C3
        float d = va.x * u4.x + va.y * u4.y + va.z * u4.z + va.w * u4.w;
        d = warpSum(d);
        const float e = __expf(d);
        if (lane == 0) out[(size_t)b * M_ + sp * 32 + ml] = d;  // prob_logit
        acc.x += e * vb.x; acc.y += e * vb.y;
        acc.z += e * vb.z; acc.w += e * vb.w;
        den += e;
    }
    reinterpret_cast<float4*>(&s_pt[wid][0])[lane] = acc;
    if (lane == 0) s_den[wid] = den;
    __syncthreads();

    if (tid < D_) {
        float v = 0.f;
        #pragma unroll
        for (int g = 0; g < 8; g++) v += s_pt[g][tid];
        g_partF[(size_t)blk * D_ + tid] = v;     // reuse partF for hop-2
    }
    if (tid == 0) {
        float dn = 0.f;
        #pragma unroll
        for (int g = 0; g < 8; g++) dn += s_den[g];
        g_denF[blk] = dn;
    }
    __syncthreads();

    // ---- last-block-per-batch: u3 -> out ----
    if (tid == 0) {
        __threadfence();
        const unsigned old = atomicAdd(&g_cnt[b], 1u);
        s_last = (old == FSPL - 1);
    }
    __syncthreads();
    if (s_last) {
        __threadfence();   // acquire peers' partial writes
        if (tid < D_) {
            float dn = 0.f;
            #pragma unroll
            for (int k = 0; k < FSPL; k++) dn += g_denF[b * FSPL + k];
            float num = 0.f;
            #pragma unroll
            for (int k = 0; k < FSPL; k++) num += g_partF[((size_t)b * FSPL + k) * D_ + tid];
            out[(size_t)B_ * M_ + (size_t)b * D_ + tid] = s_u[tid] + num / dn;
        }
        if (tid == 0) g_cnt[b] = 0;   // reset for next replay
    }
}

extern "C" void kernel_launch(void* const* d_in, const int* in_sizes, int n_in,
                              void* d_out, int out_size)
{
    const int*   story  = (const int*)  d_in[0];   // [B, M, S] int32
    const float* hidden = (const float*)d_in[1];   // [B, 1, D] f32
    const float* C      = (const float*)d_in[2];   // [4, V, D] f32
    float* out = (float*)d_out;                    // [B*M] logits ++ [B*D] u

    k_gather<<<GBLK, 256>>>(story, hidden, C);     // hop-0 fused
    k_F1    <<<B_ * FSPL, 256>>>(hidden);          // u1 + hop-1 pass
    k_F2    <<<B_ * FSPL, 256>>>(out);             // u2 + hop-2 + final u3
}